// round 6
// baseline (speedup 1.0000x reference)
#include <cuda_runtime.h>
#include <cstdint>

// Problem constants
#define BB 16
#define TT 1024
#define DD 1024

// GEMM tile config: CTA 256x128, warp tile 64x64 (4x2 warp grid), 4-stage cp.async
constexpr int BM = 256, BN = 128, BK = 16, STAGES = 4;
constexpr int LDT = BK + 4;     // [rows][K] pitch (floats): conflict-free for ldmatrix
constexpr int LDN = 128 + 8;    // [K][N] pitch: 136 mod 32 = 8 -> conflict-free LDS
constexpr int NTHREADS = 256;

constexpr int ASZ   = BM * LDT;               // floats per A stage (5120)
constexpr int BSZ_T = BN * LDT;               // floats per B stage, TRANSB (2560)
constexpr int BSZ_N = BK * LDN;               // floats per B stage, natural (2176)
constexpr int SMEM_T = STAGES * (ASZ + BSZ_T) * 4;   // 122880 B
constexpr int SMEM_N = STAGES * (ASZ + BSZ_N) * 4;   // 116736 B

// Scratch (device globals: allocation-free rule)
__device__ float g_Q[16777216];   // B*T*D  (tf32-rounded)
__device__ float g_K[16777216];
__device__ float g_V[16777216];
__device__ float g_S[16777216];   // B*T*T: raw scores, then rounded P in place
__device__ float g_Xq[16777216];  // tf32-rounded input copies
__device__ float g_Xk[16777216];
__device__ float g_Xv[16777216];
__device__ float g_W[3 * 1048576];// tf32-rounded Wq|Wk|Wv

__device__ __forceinline__ uint32_t f2tf(float x) {
    uint32_t u;
    asm("cvt.rna.tf32.f32 %0, %1;" : "=r"(u) : "f"(x));
    return u;
}
__device__ __forceinline__ float tf32r(float x) { return __uint_as_float(f2tf(x)); }

__device__ __forceinline__ void mma8(float* c, const uint32_t* a, const uint32_t* b) {
    asm volatile(
        "mma.sync.aligned.m16n8k8.row.col.f32.tf32.tf32.f32 "
        "{%0,%1,%2,%3},{%4,%5,%6,%7},{%8,%9},{%0,%1,%2,%3};"
        : "+f"(c[0]), "+f"(c[1]), "+f"(c[2]), "+f"(c[3])
        : "r"(a[0]), "r"(a[1]), "r"(a[2]), "r"(a[3]), "r"(b[0]), "r"(b[1]));
}
__device__ __forceinline__ void ldsm4(uint32_t* r, uint32_t addr) {
    asm volatile("ldmatrix.sync.aligned.m8n8.x4.shared.b16 {%0,%1,%2,%3}, [%4];"
                 : "=r"(r[0]), "=r"(r[1]), "=r"(r[2]), "=r"(r[3]) : "r"(addr));
}
__device__ __forceinline__ void cp16(uint32_t dst, const float* src) {
    asm volatile("cp.async.ca.shared.global [%0], [%1], 16;" :: "r"(dst), "l"(src));
}
__device__ __forceinline__ void cp_commit() { asm volatile("cp.async.commit_group;"); }
__device__ __forceinline__ uint32_t smem_u32(const void* p) {
    uint32_t a;
    asm("{ .reg .u64 t; cvta.to.shared.u64 t, %1; cvt.u32.u64 %0, t; }" : "=r"(a) : "l"(p));
    return a;
}

// C[M,N] = A[M,K] * op(B) (+bias) (*scale) (tf32-round output)
// TRANSB=true : B is [N,K] row-major (C = A @ B^T), staged [N][K]
// TRANSB=false: B is [K,N] row-major (C = A @ B),   staged [K][N]
template <bool TRANSB, bool HASBIAS, bool HASSCALE, bool ROUNDOUT>
__device__ __forceinline__ void gemm_body(
    const float* __restrict__ A, const float* __restrict__ Bm,
    const float* __restrict__ bias, float* __restrict__ C,
    int m0, int n0, int KT, int lda, int ldb, int ldc, float scale)
{
    extern __shared__ __align__(16) float smem[];
    constexpr int BSZ = TRANSB ? BSZ_T : BSZ_N;

    const int tid  = threadIdx.x;
    const int warp = tid >> 5, lane = tid & 31;
    const int g = lane >> 2, t4 = lane & 3;
    const int wM = (warp >> 1) * 64;   // 0,64,128,192
    const int wN = (warp & 1) * 64;    // 0,64
    const int lg = lane >> 3, lr = lane & 7;

    // gmem->smem copy mappings (16B chunks)
    const int aRow = tid >> 2;          // 0..63 (slices +64,+128,+192)
    const int aCol = (tid & 3) << 2;    // 0,4,8,12
    const int bK = tid & 15;            // natural-layout mapping
    const int bN = (tid >> 4) << 2;

    const uint32_t sBase  = smem_u32(smem);
    const uint32_t asBase = sBase;
    const uint32_t bsBase = sBase + STAGES * ASZ * 4;

    uint32_t aOff[4];
#pragma unroll
    for (int s = 0; s < 4; s++)
        aOff[s] = (uint32_t)(((aRow + s * 64) * LDT + aCol) * 4);
    const uint32_t bOff0 = TRANSB ? aOff[0] : (uint32_t)((bK * LDN + bN) * 4);
    const uint32_t bOff1 = TRANSB ? aOff[1] : (uint32_t)((bK * LDN + bN + 64) * 4);

    // ldmatrix fragment base offsets (bytes)
    const uint32_t aFrag = (uint32_t)(((wM + (lg & 1) * 8 + lr) * LDT + (lg >> 1) * 4) * 4);
    const uint32_t bFrag = (uint32_t)(((wN + (lg >> 1) * 8 + lr) * LDT + (lg & 1) * 4) * 4);

    float acc[4][8][4];
#pragma unroll
    for (int mf = 0; mf < 4; mf++)
#pragma unroll
        for (int nf = 0; nf < 8; nf++)
#pragma unroll
            for (int c = 0; c < 4; c++) acc[mf][nf][c] = 0.f;

    auto issue = [&](int kt) {
        if (kt < KT) {
            const int s = kt % STAGES;
            const int kOff = kt * BK;
            const uint32_t asb = asBase + (uint32_t)(s * ASZ * 4);
            const uint32_t bsb = bsBase + (uint32_t)(s * BSZ * 4);
#pragma unroll
            for (int sl = 0; sl < 4; sl++)
                cp16(asb + aOff[sl], A + (size_t)(m0 + aRow + sl * 64) * lda + kOff + aCol);
            if (TRANSB) {
                cp16(bsb + bOff0, Bm + (size_t)(n0 + aRow) * ldb + kOff + aCol);
                cp16(bsb + bOff1, Bm + (size_t)(n0 + aRow + 64) * ldb + kOff + aCol);
            } else {
                cp16(bsb + bOff0, Bm + (size_t)(kOff + bK) * ldb + n0 + bN);
                cp16(bsb + bOff1, Bm + (size_t)(kOff + bK) * ldb + n0 + bN + 64);
            }
        }
        cp_commit();
    };

#pragma unroll
    for (int s = 0; s < STAGES - 1; s++) issue(s);

    for (int kt = 0; kt < KT; ++kt) {
        const int cur = kt % STAGES;
        asm volatile("cp.async.wait_group %0;" :: "n"(STAGES - 2));
        __syncthreads();               // stage kt ready; all warps done with stage kt-1

        issue(kt + STAGES - 1);

        const uint32_t asb = asBase + (uint32_t)(cur * ASZ * 4);
        const uint32_t bsb = bsBase + (uint32_t)(cur * BSZ * 4);
        const float* Bsp = smem + STAGES * ASZ + cur * BSZ;
#pragma unroll
        for (int k8 = 0; k8 < BK; k8 += 8) {
            uint32_t af[4][4], bf[8][2];
#pragma unroll
            for (int mf = 0; mf < 4; mf++)
                ldsm4(af[mf], asb + aFrag + (uint32_t)((mf * 16 * LDT + k8) * 4));
            if (TRANSB) {
#pragma unroll
                for (int np = 0; np < 4; np++)
                    ldsm4(&bf[2 * np][0], bsb + bFrag + (uint32_t)((np * 16 * LDT + k8) * 4));
            } else {
#pragma unroll
                for (int nf = 0; nf < 8; nf++) {
                    const float* p = Bsp + (k8 + t4) * LDN + wN + nf * 8 + g;
                    bf[nf][0] = __float_as_uint(p[0]);
                    bf[nf][1] = __float_as_uint(p[4 * LDN]);
                }
            }
#pragma unroll
            for (int mf = 0; mf < 4; mf++)
#pragma unroll
                for (int nf = 0; nf < 8; nf++)
                    mma8(acc[mf][nf], af[mf], bf[nf]);
        }
    }

    // epilogue
#pragma unroll
    for (int mf = 0; mf < 4; mf++) {
        const int r0 = m0 + wM + mf * 16 + g;
#pragma unroll
        for (int nf = 0; nf < 8; nf++) {
            const int col = n0 + wN + nf * 8 + 2 * t4;
            float v0 = acc[mf][nf][0], v1 = acc[mf][nf][1];
            float v2 = acc[mf][nf][2], v3 = acc[mf][nf][3];
            if (HASSCALE) { v0 *= scale; v1 *= scale; v2 *= scale; v3 *= scale; }
            if (HASBIAS) {
                float2 bv = *(const float2*)(bias + col);
                v0 += bv.x; v1 += bv.y; v2 += bv.x; v3 += bv.y;
            }
            if (ROUNDOUT) { v0 = tf32r(v0); v1 = tf32r(v1); v2 = tf32r(v2); v3 = tf32r(v3); }
            float2 o;
            o.x = v0; o.y = v1;
            *(float2*)(C + (size_t)r0 * ldc + col) = o;
            o.x = v2; o.y = v3;
            *(float2*)(C + (size_t)(r0 + 8) * ldc + col) = o;
        }
    }
}

// ---- Stage 0: tf32 pre-round of inputs and weights ----
__global__ void __launch_bounds__(256) roundX_kernel(
    const float* __restrict__ a, const float* __restrict__ b, const float* __restrict__ c)
{
    const int i = blockIdx.x * 256 + threadIdx.x;
    const int z = blockIdx.y;
    const float* s = (z == 0) ? a : (z == 1) ? b : c;
    float* d = (z == 0) ? g_Xq : (z == 1) ? g_Xk : g_Xv;
    float4 v = ((const float4*)s)[i];
    v.x = tf32r(v.x); v.y = tf32r(v.y); v.z = tf32r(v.z); v.w = tf32r(v.w);
    ((float4*)d)[i] = v;
}
__global__ void __launch_bounds__(256) roundW_kernel(
    const float* __restrict__ a, const float* __restrict__ b, const float* __restrict__ c)
{
    const int i = blockIdx.x * 256 + threadIdx.x;
    const int z = blockIdx.y;
    const float* s = (z == 0) ? a : (z == 1) ? b : c;
    float* d = g_W + (size_t)z * 1048576;
    float4 v = ((const float4*)s)[i];
    v.x = tf32r(v.x); v.y = tf32r(v.y); v.z = tf32r(v.z); v.w = tf32r(v.w);
    ((float4*)d)[i] = v;
}

// ---- Stage 1: Q/K/V projections (rounded outputs) ----
__global__ void __launch_bounds__(NTHREADS) proj_kernel(
    const float* __restrict__ bq, const float* __restrict__ bk, const float* __restrict__ bv)
{
    const int z = blockIdx.z;
    const float* X = (z == 0) ? g_Xq : (z == 1) ? g_Xk : g_Xv;
    const float* W = g_W + (size_t)z * 1048576;
    const float* b = (z == 0) ? bq : (z == 1) ? bk : bv;
    float* O = (z == 0) ? g_Q : (z == 1) ? g_K : g_V;
    gemm_body<true, true, false, true>(X, W, b, O,
                                       blockIdx.y * BM, blockIdx.x * BN,
                                       DD / BK, DD, DD, DD, 1.f);
}

// ---- Stage 2: S = Q K^T / sqrt(D), causal tile skip ----
__global__ void __launch_bounds__(NTHREADS) qk_kernel() {
    if ((int)blockIdx.x > 2 * (int)blockIdx.y + 1) return;   // fully-masked 256x128 tile
    const int b = blockIdx.z;
    const float* Q = g_Q + (size_t)b * TT * DD;
    const float* K = g_K + (size_t)b * TT * DD;
    float* S = g_S + (size_t)b * TT * TT;
    gemm_body<true, false, true, false>(Q, K, nullptr, S,
                                        blockIdx.y * BM, blockIdx.x * BN,
                                        DD / BK, DD, DD, TT, 0.03125f);
}

// ---- Stage 3: causal row softmax, in place (rounded P) ----
__global__ void __launch_bounds__(256) softmax_kernel() {
    const int r = blockIdx.x;
    const int i = r & (TT - 1);
    float* row = g_S + (size_t)r * TT;
    const int tid = threadIdx.x;
    const int warp = tid >> 5, lane = tid & 31;
    const int j0 = tid * 4;

    float4 v = ((const float4*)row)[tid];
    float s0 = v.x, s1 = v.y, s2 = v.z, s3 = v.w;

    float m = -3.4e38f;
    if (j0 + 0 <= i) m = fmaxf(m, s0);
    if (j0 + 1 <= i) m = fmaxf(m, s1);
    if (j0 + 2 <= i) m = fmaxf(m, s2);
    if (j0 + 3 <= i) m = fmaxf(m, s3);

    __shared__ float red[8];
#pragma unroll
    for (int off = 16; off >= 1; off >>= 1)
        m = fmaxf(m, __shfl_xor_sync(0xffffffffu, m, off));
    if (lane == 0) red[warp] = m;
    __syncthreads();
    m = red[0];
#pragma unroll
    for (int w = 1; w < 8; w++) m = fmaxf(m, red[w]);

    float e0 = (j0 + 0 <= i) ? expf(s0 - m) : 0.f;
    float e1 = (j0 + 1 <= i) ? expf(s1 - m) : 0.f;
    float e2 = (j0 + 2 <= i) ? expf(s2 - m) : 0.f;
    float e3 = (j0 + 3 <= i) ? expf(s3 - m) : 0.f;
    float lsum = e0 + e1 + e2 + e3;

    __syncthreads();
#pragma unroll
    for (int off = 16; off >= 1; off >>= 1)
        lsum += __shfl_xor_sync(0xffffffffu, lsum, off);
    if (lane == 0) red[warp] = lsum;
    __syncthreads();
    float tot = red[0];
#pragma unroll
    for (int w = 1; w < 8; w++) tot += red[w];
    const float inv = 1.f / tot;

    v.x = tf32r(e0 * inv); v.y = tf32r(e1 * inv);
    v.z = tf32r(e2 * inv); v.w = tf32r(e3 * inv);
    ((float4*)row)[tid] = v;
}

// ---- Stage 4: O = P V, causal K-limit ----
__global__ void __launch_bounds__(NTHREADS) pv_kernel(float* __restrict__ out) {
    const int b = blockIdx.z;
    const int m0 = blockIdx.y * BM;
    const float* P = g_S + (size_t)b * TT * TT;
    const float* V = g_V + (size_t)b * TT * DD;
    float* O = out + (size_t)b * TT * DD;
    const int KT = (m0 + BM) / BK;   // only k <= m0+255 can be nonzero
    gemm_body<false, false, false, false>(P, V, nullptr, O,
                                          m0, blockIdx.x * BN,
                                          KT, TT, DD, DD, 1.f);
}

extern "C" void kernel_launch(void* const* d_in, const int* in_sizes, int n_in,
                              void* d_out, int out_size) {
    const float* qe = (const float*)d_in[0];
    const float* ke = (const float*)d_in[1];
    const float* ve = (const float*)d_in[2];
    const float* Wq = (const float*)d_in[3];
    const float* bq = (const float*)d_in[4];
    const float* Wk = (const float*)d_in[5];
    const float* bk = (const float*)d_in[6];
    const float* Wv = (const float*)d_in[7];
    const float* bv = (const float*)d_in[8];
    float* out = (float*)d_out;

    cudaFuncSetAttribute(proj_kernel, cudaFuncAttributeMaxDynamicSharedMemorySize, SMEM_T);
    cudaFuncSetAttribute(qk_kernel,   cudaFuncAttributeMaxDynamicSharedMemorySize, SMEM_T);
    cudaFuncSetAttribute(pv_kernel,   cudaFuncAttributeMaxDynamicSharedMemorySize, SMEM_N);

    roundX_kernel<<<dim3(16777216 / 4 / 256, 3), 256>>>(qe, ke, ve);
    roundW_kernel<<<dim3(1048576 / 4 / 256, 3), 256>>>(Wq, Wk, Wv);
    proj_kernel<<<dim3(DD / BN, (BB * TT) / BM, 3), NTHREADS, SMEM_T>>>(bq, bk, bv);
    qk_kernel<<<dim3(TT / BN, TT / BM, BB), NTHREADS, SMEM_T>>>();
    softmax_kernel<<<dim3(BB * TT), 256>>>();
    pv_kernel<<<dim3(DD / BN, TT / BM, BB), NTHREADS, SMEM_N>>>(out);
}

// round 7
// speedup vs baseline: 2.2887x; 2.2887x over previous
#include <cuda_runtime.h>
#include <cuda_fp16.h>
#include <cstdint>

// Problem constants
#define BB 16
#define TT 1024
#define DD 1024

// GEMM tile config: CTA 128x128, warp tile 64x32 (2x4), BK=32 halfs, 3-stage cp.async
constexpr int BM = 128, BN = 128, BK = 32, STAGES = 3;
constexpr int LDH  = BK + 8;     // A / B^T pitch in halfs (40): conflict-free ldmatrix
constexpr int LDBN = 128 + 8;    // natural B pitch in halfs (136): conflict-free trans-ldmatrix
constexpr int NTHREADS = 256;

constexpr int ASZ   = BM * LDH;                 // halfs per A stage (5120)
constexpr int BSZ_T = BN * LDH;                 // halfs per B stage, TRANSB
constexpr int BSZ_N = BK * LDBN;                // halfs per B stage, natural (4352)
constexpr int SMEM_T = STAGES * (ASZ + BSZ_T) * 2;   // 61440 B
constexpr int SMEM_N = STAGES * (ASZ + BSZ_N) * 2;   // 56832 B

// Scratch (device globals: allocation-free rule)
__device__ __align__(16) __half g_Q[16777216];    // B*T*D half
__device__ __align__(16) __half g_K[16777216];
__device__ __align__(16) __half g_V[16777216];
__device__ __align__(16) __half g_P[16777216];    // softmax probs, half
__device__ __align__(16) float  g_S[16777216];    // raw scores, fp32
__device__ __align__(16) __half g_Xq[16777216];   // half-rounded inputs
__device__ __align__(16) __half g_Xk[16777216];
__device__ __align__(16) __half g_Xv[16777216];
__device__ __align__(16) __half g_W[3 * 1048576]; // half-rounded Wq|Wk|Wv

__device__ __forceinline__ void mma16(float* c, const uint32_t* a, const uint32_t* b) {
    asm volatile(
        "mma.sync.aligned.m16n8k16.row.col.f32.f16.f16.f32 "
        "{%0,%1,%2,%3},{%4,%5,%6,%7},{%8,%9},{%0,%1,%2,%3};"
        : "+f"(c[0]), "+f"(c[1]), "+f"(c[2]), "+f"(c[3])
        : "r"(a[0]), "r"(a[1]), "r"(a[2]), "r"(a[3]), "r"(b[0]), "r"(b[1]));
}
__device__ __forceinline__ void ldsm4(uint32_t* r, uint32_t addr) {
    asm volatile("ldmatrix.sync.aligned.m8n8.x4.shared.b16 {%0,%1,%2,%3}, [%4];"
                 : "=r"(r[0]), "=r"(r[1]), "=r"(r[2]), "=r"(r[3]) : "r"(addr));
}
__device__ __forceinline__ void ldsm4t(uint32_t* r, uint32_t addr) {
    asm volatile("ldmatrix.sync.aligned.m8n8.x4.trans.shared.b16 {%0,%1,%2,%3}, [%4];"
                 : "=r"(r[0]), "=r"(r[1]), "=r"(r[2]), "=r"(r[3]) : "r"(addr));
}
__device__ __forceinline__ void cp16(uint32_t dst, const void* src) {
    asm volatile("cp.async.ca.shared.global [%0], [%1], 16;" :: "r"(dst), "l"(src));
}
__device__ __forceinline__ void cp_commit() { asm volatile("cp.async.commit_group;"); }
__device__ __forceinline__ uint32_t smem_u32(const void* p) {
    uint32_t a;
    asm("{ .reg .u64 t; cvta.to.shared.u64 t, %1; cvt.u32.u64 %0, t; }" : "=r"(a) : "l"(p));
    return a;
}

// C[M,N] = A[M,K] * op(B) (+bias) (*scale); A,B half; C fp32 or half
// TRANSB=true : B is [N,K] row-major (C = A @ B^T), staged [N][K] pitch LDH
// TRANSB=false: B is [K,N] row-major (C = A @ B),   staged [K][N] pitch LDBN
template <bool TRANSB, bool HASBIAS, bool HASSCALE, bool OUTHALF>
__device__ __forceinline__ void gemm_body(
    const __half* __restrict__ A, const __half* __restrict__ Bm,
    const float* __restrict__ bias, float* __restrict__ Cf, __half* __restrict__ Ch,
    int m0, int n0, int KT, int lda, int ldb, int ldc, float scale)
{
    extern __shared__ __align__(16) __half smem[];
    constexpr int BSZ = TRANSB ? BSZ_T : BSZ_N;

    const int tid  = threadIdx.x;
    const int warp = tid >> 5, lane = tid & 31;
    const int g = lane >> 2, t4 = lane & 3;
    const int wM = (warp >> 2) * 64;   // 0 or 64
    const int wN = (warp & 3) * 32;    // 0,32,64,96
    const int lg = lane >> 3, lr = lane & 7;

    // gmem->smem copy mappings (16B = 8-half chunks)
    const int aRow = tid >> 2;          // 0..63 (and +64)
    const int aCh  = (tid & 3) * 8;     // 0,8,16,24 halfs
    const int vRow = tid >> 3;          // 0..31 (natural B)
    const int vCh  = (tid & 7) * 8;     // 0..56 halfs (and +64)

    const uint32_t sBase  = smem_u32(smem);
    const uint32_t asBase = sBase;
    const uint32_t bsBase = sBase + STAGES * ASZ * 2;

    const uint32_t aOff0 = (uint32_t)((aRow * LDH + aCh) * 2);
    const uint32_t aOff1 = (uint32_t)(((aRow + 64) * LDH + aCh) * 2);
    const uint32_t bOff0 = TRANSB ? aOff0 : (uint32_t)((vRow * LDBN + vCh) * 2);
    const uint32_t bOff1 = TRANSB ? aOff1 : (uint32_t)((vRow * LDBN + vCh + 64) * 2);

    // ldmatrix fragment base offsets (bytes)
    const uint32_t aFrag  = (uint32_t)(((wM + (lg & 1) * 8 + lr) * LDH + (lg >> 1) * 8) * 2);
    const uint32_t bFragT = (uint32_t)(((wN + (lg >> 1) * 8 + lr) * LDH + (lg & 1) * 8) * 2);
    const uint32_t bFragN = (uint32_t)((((lg & 1) * 8 + lr) * LDBN + wN + (lg >> 1) * 8) * 2);

    float acc[4][4][4];
#pragma unroll
    for (int mf = 0; mf < 4; mf++)
#pragma unroll
        for (int nf = 0; nf < 4; nf++)
#pragma unroll
            for (int c = 0; c < 4; c++) acc[mf][nf][c] = 0.f;

    auto issue = [&](int kt) {
        if (kt < KT) {
            const int s = kt % STAGES;
            const int kOff = kt * BK;
            const uint32_t asb = asBase + (uint32_t)(s * ASZ * 2);
            const uint32_t bsb = bsBase + (uint32_t)(s * BSZ * 2);
            cp16(asb + aOff0, A + (size_t)(m0 + aRow) * lda + kOff + aCh);
            cp16(asb + aOff1, A + (size_t)(m0 + aRow + 64) * lda + kOff + aCh);
            if (TRANSB) {
                cp16(bsb + bOff0, Bm + (size_t)(n0 + aRow) * ldb + kOff + aCh);
                cp16(bsb + bOff1, Bm + (size_t)(n0 + aRow + 64) * ldb + kOff + aCh);
            } else {
                cp16(bsb + bOff0, Bm + (size_t)(kOff + vRow) * ldb + n0 + vCh);
                cp16(bsb + bOff1, Bm + (size_t)(kOff + vRow) * ldb + n0 + vCh + 64);
            }
        }
        cp_commit();
    };

#pragma unroll
    for (int s = 0; s < STAGES - 1; s++) issue(s);

    for (int kt = 0; kt < KT; ++kt) {
        const int cur = kt % STAGES;
        asm volatile("cp.async.wait_group %0;" :: "n"(STAGES - 2));
        __syncthreads();               // stage kt ready; all warps done with stage kt-1

        issue(kt + STAGES - 1);

        const uint32_t asb = asBase + (uint32_t)(cur * ASZ * 2);
        const uint32_t bsb = bsBase + (uint32_t)(cur * BSZ * 2);
#pragma unroll
        for (int k16 = 0; k16 < BK; k16 += 16) {
            uint32_t af[4][4], bf[4][2];
#pragma unroll
            for (int mf = 0; mf < 4; mf++)
                ldsm4(af[mf], asb + aFrag + (uint32_t)((mf * 16 * LDH + k16) * 2));
            if (TRANSB) {
#pragma unroll
                for (int np = 0; np < 2; np++)
                    ldsm4(&bf[2 * np][0],
                          bsb + bFragT + (uint32_t)((np * 16 * LDH + k16) * 2));
            } else {
#pragma unroll
                for (int np = 0; np < 2; np++)
                    ldsm4t(&bf[2 * np][0],
                           bsb + bFragN + (uint32_t)((k16 * LDBN + np * 16) * 2));
            }
#pragma unroll
            for (int mf = 0; mf < 4; mf++)
#pragma unroll
                for (int nf = 0; nf < 4; nf++)
                    mma16(acc[mf][nf], af[mf], bf[nf]);
        }
    }

    // epilogue
#pragma unroll
    for (int mf = 0; mf < 4; mf++) {
        const int r0 = m0 + wM + mf * 16 + g;
#pragma unroll
        for (int nf = 0; nf < 4; nf++) {
            const int col = n0 + wN + nf * 8 + 2 * t4;
            float v0 = acc[mf][nf][0], v1 = acc[mf][nf][1];
            float v2 = acc[mf][nf][2], v3 = acc[mf][nf][3];
            if (HASSCALE) { v0 *= scale; v1 *= scale; v2 *= scale; v3 *= scale; }
            if (HASBIAS) {
                float2 bv = *(const float2*)(bias + col);
                v0 += bv.x; v1 += bv.y; v2 += bv.x; v3 += bv.y;
            }
            if (OUTHALF) {
                *(__half2*)(Ch + (size_t)r0 * ldc + col) = __floats2half2_rn(v0, v1);
                *(__half2*)(Ch + (size_t)(r0 + 8) * ldc + col) = __floats2half2_rn(v2, v3);
            } else {
                float2 o;
                o.x = v0; o.y = v1;
                *(float2*)(Cf + (size_t)r0 * ldc + col) = o;
                o.x = v2; o.y = v3;
                *(float2*)(Cf + (size_t)(r0 + 8) * ldc + col) = o;
            }
        }
    }
}

// ---- Stage 0: fp16 pre-round of inputs and weights ----
__global__ void __launch_bounds__(256) roundX_kernel(
    const float* __restrict__ a, const float* __restrict__ b, const float* __restrict__ c)
{
    const int i = (blockIdx.x * 256 + threadIdx.x) * 8;
    const int z = blockIdx.y;
    const float* s = (z == 0) ? a : (z == 1) ? b : c;
    __half* d = (z == 0) ? g_Xq : (z == 1) ? g_Xk : g_Xv;
    float4 v0 = *(const float4*)(s + i);
    float4 v1 = *(const float4*)(s + i + 4);
    __half2 h[4] = { __floats2half2_rn(v0.x, v0.y), __floats2half2_rn(v0.z, v0.w),
                     __floats2half2_rn(v1.x, v1.y), __floats2half2_rn(v1.z, v1.w) };
    *(uint4*)(d + i) = *(const uint4*)h;
}
__global__ void __launch_bounds__(256) roundW_kernel(
    const float* __restrict__ a, const float* __restrict__ b, const float* __restrict__ c)
{
    const int i = (blockIdx.x * 256 + threadIdx.x) * 8;
    const int z = blockIdx.y;
    const float* s = (z == 0) ? a : (z == 1) ? b : c;
    __half* d = g_W + (size_t)z * 1048576;
    float4 v0 = *(const float4*)(s + i);
    float4 v1 = *(const float4*)(s + i + 4);
    __half2 h[4] = { __floats2half2_rn(v0.x, v0.y), __floats2half2_rn(v0.z, v0.w),
                     __floats2half2_rn(v1.x, v1.y), __floats2half2_rn(v1.z, v1.w) };
    *(uint4*)(d + i) = *(const uint4*)h;
}

// ---- Stage 1: Q/K/V projections (half outputs) ----
__global__ void __launch_bounds__(NTHREADS, 2) proj_kernel(
    const float* __restrict__ bq, const float* __restrict__ bk, const float* __restrict__ bv)
{
    const int z = blockIdx.z;
    const __half* X = (z == 0) ? g_Xq : (z == 1) ? g_Xk : g_Xv;
    const __half* W = g_W + (size_t)z * 1048576;
    const float* b = (z == 0) ? bq : (z == 1) ? bk : bv;
    __half* O = (z == 0) ? g_Q : (z == 1) ? g_K : g_V;
    gemm_body<true, true, false, true>(X, W, b, nullptr, O,
                                       blockIdx.y * BM, blockIdx.x * BN,
                                       DD / BK, DD, DD, DD, 1.f);
}

// ---- Stage 2: S = Q K^T / sqrt(D) (fp32 scores), causal tile skip ----
__global__ void __launch_bounds__(NTHREADS, 2) qk_kernel() {
    if (blockIdx.x > blockIdx.y) return;   // fully-masked 128x128 tile
    const int b = blockIdx.z;
    const __half* Q = g_Q + (size_t)b * TT * DD;
    const __half* K = g_K + (size_t)b * TT * DD;
    float* S = g_S + (size_t)b * TT * TT;
    gemm_body<true, false, true, false>(Q, K, nullptr, S, nullptr,
                                        blockIdx.y * BM, blockIdx.x * BN,
                                        DD / BK, DD, DD, TT, 0.03125f);
}

// ---- Stage 3: causal row softmax (fp32 in, half P out) ----
__global__ void __launch_bounds__(256) softmax_kernel() {
    const int r = blockIdx.x;              // 0 .. B*T-1
    const int i = r & (TT - 1);
    const float* row = g_S + (size_t)r * TT;
    __half* prow = g_P + (size_t)r * TT;
    const int tid = threadIdx.x;
    const int warp = tid >> 5, lane = tid & 31;
    const int j0 = tid * 4;

    float4 v = ((const float4*)row)[tid];
    float s0 = v.x, s1 = v.y, s2 = v.z, s3 = v.w;

    float m = -3.4e38f;
    if (j0 + 0 <= i) m = fmaxf(m, s0);
    if (j0 + 1 <= i) m = fmaxf(m, s1);
    if (j0 + 2 <= i) m = fmaxf(m, s2);
    if (j0 + 3 <= i) m = fmaxf(m, s3);

    __shared__ float red[8];
#pragma unroll
    for (int off = 16; off >= 1; off >>= 1)
        m = fmaxf(m, __shfl_xor_sync(0xffffffffu, m, off));
    if (lane == 0) red[warp] = m;
    __syncthreads();
    m = red[0];
#pragma unroll
    for (int w = 1; w < 8; w++) m = fmaxf(m, red[w]);

    float e0 = (j0 + 0 <= i) ? expf(s0 - m) : 0.f;
    float e1 = (j0 + 1 <= i) ? expf(s1 - m) : 0.f;
    float e2 = (j0 + 2 <= i) ? expf(s2 - m) : 0.f;
    float e3 = (j0 + 3 <= i) ? expf(s3 - m) : 0.f;
    float lsum = e0 + e1 + e2 + e3;

    __syncthreads();
#pragma unroll
    for (int off = 16; off >= 1; off >>= 1)
        lsum += __shfl_xor_sync(0xffffffffu, lsum, off);
    if (lane == 0) red[warp] = lsum;
    __syncthreads();
    float tot = red[0];
#pragma unroll
    for (int w = 1; w < 8; w++) tot += red[w];
    const float inv = 1.f / tot;

    __half2 h0 = __floats2half2_rn(e0 * inv, e1 * inv);
    __half2 h1 = __floats2half2_rn(e2 * inv, e3 * inv);
    __half2 hp[2] = {h0, h1};
    *(uint2*)(prow + j0) = *(const uint2*)hp;
}

// ---- Stage 4: O = P V (fp32 out), causal K-limit ----
__global__ void __launch_bounds__(NTHREADS, 2) pv_kernel(float* __restrict__ out) {
    const int b = blockIdx.z;
    const int m0 = blockIdx.y * BM;
    const __half* P = g_P + (size_t)b * TT * TT;
    const __half* V = g_V + (size_t)b * TT * DD;
    float* O = out + (size_t)b * TT * DD;
    const int KT = (m0 + BM) / BK;   // only k <= m0+127 can be nonzero
    gemm_body<false, false, false, false>(P, V, nullptr, O, nullptr,
                                          m0, blockIdx.x * BN,
                                          KT, TT, DD, DD, 1.f);
}

extern "C" void kernel_launch(void* const* d_in, const int* in_sizes, int n_in,
                              void* d_out, int out_size) {
    const float* qe = (const float*)d_in[0];
    const float* ke = (const float*)d_in[1];
    const float* ve = (const float*)d_in[2];
    const float* Wq = (const float*)d_in[3];
    const float* bq = (const float*)d_in[4];
    const float* Wk = (const float*)d_in[5];
    const float* bk = (const float*)d_in[6];
    const float* Wv = (const float*)d_in[7];
    const float* bv = (const float*)d_in[8];
    float* out = (float*)d_out;

    cudaFuncSetAttribute(proj_kernel, cudaFuncAttributeMaxDynamicSharedMemorySize, SMEM_T);
    cudaFuncSetAttribute(qk_kernel,   cudaFuncAttributeMaxDynamicSharedMemorySize, SMEM_T);
    cudaFuncSetAttribute(pv_kernel,   cudaFuncAttributeMaxDynamicSharedMemorySize, SMEM_N);

    roundX_kernel<<<dim3(16777216 / 8 / 256, 3), 256>>>(qe, ke, ve);
    roundW_kernel<<<dim3(1048576 / 8 / 256, 3), 256>>>(Wq, Wk, Wv);
    proj_kernel<<<dim3(DD / BN, (BB * TT) / BM, 3), NTHREADS, SMEM_T>>>(bq, bk, bv);
    qk_kernel<<<dim3(TT / BN, TT / BM, BB), NTHREADS, SMEM_T>>>();
    softmax_kernel<<<dim3(BB * TT), 256>>>();
    pv_kernel<<<dim3(DD / BN, TT / BM, BB), NTHREADS, SMEM_N>>>(out);
}

// round 8
// speedup vs baseline: 2.5359x; 1.1080x over previous
#include <cuda_runtime.h>
#include <cuda_fp16.h>
#include <cstdint>

// Problem constants
#define BB 16
#define TT 1024
#define DD 1024

// GEMM tile config: CTA 128x128 (4 warps), warp tile 64x64 (2x2), BK=32, 3-stage cp.async
constexpr int BM = 128, BN = 128, BK = 32, STAGES = 3;
constexpr int LDH  = BK + 8;     // A / B^T pitch in halfs (40)
constexpr int LDBN = 128 + 8;    // natural B pitch in halfs (136)
constexpr int NTHREADS = 128;

constexpr int ASZ   = BM * LDH;                 // halfs per A stage
constexpr int BSZ_T = BN * LDH;
constexpr int BSZ_N = BK * LDBN;
constexpr int SMEM_T = STAGES * (ASZ + BSZ_T) * 2;   // 61440 B
constexpr int SMEM_N = STAGES * (ASZ + BSZ_N) * 2;   // 56832 B

// Scratch (device globals: allocation-free rule)
__device__ __align__(16) __half g_Q[16777216];    // B*T*D half
__device__ __align__(16) __half g_K[16777216];
__device__ __align__(16) __half g_V[16777216];
__device__ __align__(16) __half g_P[16777216];    // softmax probs, half
__device__ __align__(16) float  g_S[16777216];    // raw scores, fp32
__device__ __align__(16) __half g_Xq[16777216];   // half-rounded inputs
__device__ __align__(16) __half g_Xk[16777216];
__device__ __align__(16) __half g_Xv[16777216];
__device__ __align__(16) __half g_W[3 * 1048576]; // half-rounded Wq|Wk|Wv

__device__ __forceinline__ void mma16(float* c, const uint32_t* a, const uint32_t* b) {
    asm volatile(
        "mma.sync.aligned.m16n8k16.row.col.f32.f16.f16.f32 "
        "{%0,%1,%2,%3},{%4,%5,%6,%7},{%8,%9},{%0,%1,%2,%3};"
        : "+f"(c[0]), "+f"(c[1]), "+f"(c[2]), "+f"(c[3])
        : "r"(a[0]), "r"(a[1]), "r"(a[2]), "r"(a[3]), "r"(b[0]), "r"(b[1]));
}
__device__ __forceinline__ void ldsm4(uint32_t* r, uint32_t addr) {
    asm volatile("ldmatrix.sync.aligned.m8n8.x4.shared.b16 {%0,%1,%2,%3}, [%4];"
                 : "=r"(r[0]), "=r"(r[1]), "=r"(r[2]), "=r"(r[3]) : "r"(addr));
}
__device__ __forceinline__ void ldsm4t(uint32_t* r, uint32_t addr) {
    asm volatile("ldmatrix.sync.aligned.m8n8.x4.trans.shared.b16 {%0,%1,%2,%3}, [%4];"
                 : "=r"(r[0]), "=r"(r[1]), "=r"(r[2]), "=r"(r[3]) : "r"(addr));
}
__device__ __forceinline__ void cp16(uint32_t dst, const void* src) {
    asm volatile("cp.async.ca.shared.global [%0], [%1], 16;" :: "r"(dst), "l"(src));
}
__device__ __forceinline__ void cp_commit() { asm volatile("cp.async.commit_group;"); }
__device__ __forceinline__ uint32_t smem_u32(const void* p) {
    uint32_t a;
    asm("{ .reg .u64 t; cvta.to.shared.u64 t, %1; cvt.u32.u64 %0, t; }" : "=r"(a) : "l"(p));
    return a;
}

// C[M,N] = A[M,K] * op(B) (+bias) (*scale); A,B half; C fp32 or half. 128 threads.
template <bool TRANSB, bool HASBIAS, bool HASSCALE, bool OUTHALF>
__device__ __forceinline__ void gemm_body(
    const __half* __restrict__ A, const __half* __restrict__ Bm,
    const float* __restrict__ bias, float* __restrict__ Cf, __half* __restrict__ Ch,
    int m0, int n0, int KT, int lda, int ldb, int ldc, float scale)
{
    extern __shared__ __align__(16) __half smem[];
    constexpr int BSZ = TRANSB ? BSZ_T : BSZ_N;

    const int tid  = threadIdx.x;
    const int warp = tid >> 5, lane = tid & 31;
    const int g = lane >> 2, t4 = lane & 3;
    const int wM = (warp >> 1) * 64;   // 0 or 64
    const int wN = (warp & 1) * 64;    // 0 or 64
    const int lg = lane >> 3, lr = lane & 7;

    // gmem->smem copy mappings (16B = 8-half chunks), 128 threads
    const int aRow = tid >> 2;          // 0..31 (+32,+64,+96 slices)
    const int aCh  = (tid & 3) * 8;     // 0,8,16,24
    const int vRow = tid >> 4;          // 0..7  (+8,+16,+24 slices)
    const int vCh  = (tid & 15) * 8;    // 0..120

    const uint32_t sBase  = smem_u32(smem);
    const uint32_t asBase = sBase;
    const uint32_t bsBase = sBase + STAGES * ASZ * 2;

    uint32_t aOff[4], bOff[4];
#pragma unroll
    for (int s = 0; s < 4; s++) {
        aOff[s] = (uint32_t)(((aRow + s * 32) * LDH + aCh) * 2);
        bOff[s] = TRANSB ? aOff[s] : (uint32_t)(((vRow + s * 8) * LDBN + vCh) * 2);
    }

    // ldmatrix fragment base offsets (bytes)
    const uint32_t aFrag  = (uint32_t)(((wM + (lg & 1) * 8 + lr) * LDH + (lg >> 1) * 8) * 2);
    const uint32_t bFragT = (uint32_t)(((wN + (lg >> 1) * 8 + lr) * LDH + (lg & 1) * 8) * 2);
    const uint32_t bFragN = (uint32_t)((((lg & 1) * 8 + lr) * LDBN + wN + (lg >> 1) * 8) * 2);

    float acc[4][8][4];
#pragma unroll
    for (int mf = 0; mf < 4; mf++)
#pragma unroll
        for (int nf = 0; nf < 8; nf++)
#pragma unroll
            for (int c = 0; c < 4; c++) acc[mf][nf][c] = 0.f;

    auto issue = [&](int kt) {
        if (kt < KT) {
            const int s = kt % STAGES;
            const int kOff = kt * BK;
            const uint32_t asb = asBase + (uint32_t)(s * ASZ * 2);
            const uint32_t bsb = bsBase + (uint32_t)(s * BSZ * 2);
#pragma unroll
            for (int sl = 0; sl < 4; sl++)
                cp16(asb + aOff[sl], A + (size_t)(m0 + aRow + sl * 32) * lda + kOff + aCh);
            if (TRANSB) {
#pragma unroll
                for (int sl = 0; sl < 4; sl++)
                    cp16(bsb + bOff[sl], Bm + (size_t)(n0 + aRow + sl * 32) * ldb + kOff + aCh);
            } else {
#pragma unroll
                for (int sl = 0; sl < 4; sl++)
                    cp16(bsb + bOff[sl], Bm + (size_t)(kOff + vRow + sl * 8) * ldb + n0 + vCh);
            }
        }
        cp_commit();
    };

#pragma unroll
    for (int s = 0; s < STAGES - 1; s++) issue(s);

    for (int kt = 0; kt < KT; ++kt) {
        const int cur = kt % STAGES;
        asm volatile("cp.async.wait_group %0;" :: "n"(STAGES - 2));
        __syncthreads();               // stage kt ready; all warps done with stage kt-1

        issue(kt + STAGES - 1);

        const uint32_t asb = asBase + (uint32_t)(cur * ASZ * 2);
        const uint32_t bsb = bsBase + (uint32_t)(cur * BSZ * 2);
#pragma unroll
        for (int k16 = 0; k16 < BK; k16 += 16) {
            uint32_t af[4][4], bf[8][2];
#pragma unroll
            for (int mf = 0; mf < 4; mf++)
                ldsm4(af[mf], asb + aFrag + (uint32_t)((mf * 16 * LDH + k16) * 2));
            if (TRANSB) {
#pragma unroll
                for (int np = 0; np < 4; np++)
                    ldsm4(&bf[2 * np][0],
                          bsb + bFragT + (uint32_t)((np * 16 * LDH + k16) * 2));
            } else {
#pragma unroll
                for (int np = 0; np < 4; np++)
                    ldsm4t(&bf[2 * np][0],
                           bsb + bFragN + (uint32_t)((k16 * LDBN + np * 16) * 2));
            }
#pragma unroll
            for (int mf = 0; mf < 4; mf++)
#pragma unroll
                for (int nf = 0; nf < 8; nf++)
                    mma16(acc[mf][nf], af[mf], bf[nf]);
        }
    }

    // epilogue
#pragma unroll
    for (int mf = 0; mf < 4; mf++) {
        const int r0 = m0 + wM + mf * 16 + g;
#pragma unroll
        for (int nf = 0; nf < 8; nf++) {
            const int col = n0 + wN + nf * 8 + 2 * t4;
            float v0 = acc[mf][nf][0], v1 = acc[mf][nf][1];
            float v2 = acc[mf][nf][2], v3 = acc[mf][nf][3];
            if (HASSCALE) { v0 *= scale; v1 *= scale; v2 *= scale; v3 *= scale; }
            if (HASBIAS) {
                float2 bv = *(const float2*)(bias + col);
                v0 += bv.x; v1 += bv.y; v2 += bv.x; v3 += bv.y;
            }
            if (OUTHALF) {
                *(__half2*)(Ch + (size_t)r0 * ldc + col) = __floats2half2_rn(v0, v1);
                *(__half2*)(Ch + (size_t)(r0 + 8) * ldc + col) = __floats2half2_rn(v2, v3);
            } else {
                float2 o;
                o.x = v0; o.y = v1;
                *(float2*)(Cf + (size_t)r0 * ldc + col) = o;
                o.x = v2; o.y = v3;
                *(float2*)(Cf + (size_t)(r0 + 8) * ldc + col) = o;
            }
        }
    }
}

// ---- Stage 0: fp16 pre-round of inputs and weights ----
__global__ void __launch_bounds__(256) roundX_kernel(
    const float* __restrict__ a, const float* __restrict__ b, const float* __restrict__ c)
{
    const int i = (blockIdx.x * 256 + threadIdx.x) * 8;
    const int z = blockIdx.y;
    const float* s = (z == 0) ? a : (z == 1) ? b : c;
    __half* d = (z == 0) ? g_Xq : (z == 1) ? g_Xk : g_Xv;
    float4 v0 = *(const float4*)(s + i);
    float4 v1 = *(const float4*)(s + i + 4);
    __half2 h[4] = { __floats2half2_rn(v0.x, v0.y), __floats2half2_rn(v0.z, v0.w),
                     __floats2half2_rn(v1.x, v1.y), __floats2half2_rn(v1.z, v1.w) };
    *(uint4*)(d + i) = *(const uint4*)h;
}
__global__ void __launch_bounds__(256) roundW_kernel(
    const float* __restrict__ a, const float* __restrict__ b, const float* __restrict__ c)
{
    const int i = (blockIdx.x * 256 + threadIdx.x) * 8;
    const int z = blockIdx.y;
    const float* s = (z == 0) ? a : (z == 1) ? b : c;
    __half* d = g_W + (size_t)z * 1048576;
    float4 v0 = *(const float4*)(s + i);
    float4 v1 = *(const float4*)(s + i + 4);
    __half2 h[4] = { __floats2half2_rn(v0.x, v0.y), __floats2half2_rn(v0.z, v0.w),
                     __floats2half2_rn(v1.x, v1.y), __floats2half2_rn(v1.z, v1.w) };
    *(uint4*)(d + i) = *(const uint4*)h;
}

// ---- Stage 1: Q/K/V projections (half outputs) ----
__global__ void __launch_bounds__(NTHREADS, 2) proj_kernel(
    const float* __restrict__ bq, const float* __restrict__ bk, const float* __restrict__ bv)
{
    const int z = blockIdx.z;
    const __half* X = (z == 0) ? g_Xq : (z == 1) ? g_Xk : g_Xv;
    const __half* W = g_W + (size_t)z * 1048576;
    const float* b = (z == 0) ? bq : (z == 1) ? bk : bv;
    __half* O = (z == 0) ? g_Q : (z == 1) ? g_K : g_V;
    gemm_body<true, true, false, true>(X, W, b, nullptr, O,
                                       blockIdx.y * BM, blockIdx.x * BN,
                                       DD / BK, DD, DD, DD, 1.f);
}

// ---- Stage 2: S = Q K^T / sqrt(D) (fp32 scores), causal tile skip ----
__global__ void __launch_bounds__(NTHREADS, 2) qk_kernel() {
    if (blockIdx.x > blockIdx.y) return;   // fully-masked 128x128 tile
    const int b = blockIdx.z;
    const __half* Q = g_Q + (size_t)b * TT * DD;
    const __half* K = g_K + (size_t)b * TT * DD;
    float* S = g_S + (size_t)b * TT * TT;
    gemm_body<true, false, true, false>(Q, K, nullptr, S, nullptr,
                                        blockIdx.y * BM, blockIdx.x * BN,
                                        DD / BK, DD, DD, TT, 0.03125f);
}

// ---- Stage 3: causal row softmax (fp32 in, half P out) ----
__global__ void __launch_bounds__(256) softmax_kernel() {
    const int r = blockIdx.x;              // 0 .. B*T-1
    const int i = r & (TT - 1);
    const float* row = g_S + (size_t)r * TT;
    __half* prow = g_P + (size_t)r * TT;
    const int tid = threadIdx.x;
    const int warp = tid >> 5, lane = tid & 31;
    const int j0 = tid * 4;

    float4 v = ((const float4*)row)[tid];
    float s0 = v.x, s1 = v.y, s2 = v.z, s3 = v.w;

    float m = -3.4e38f;
    if (j0 + 0 <= i) m = fmaxf(m, s0);
    if (j0 + 1 <= i) m = fmaxf(m, s1);
    if (j0 + 2 <= i) m = fmaxf(m, s2);
    if (j0 + 3 <= i) m = fmaxf(m, s3);

    __shared__ float red[8];
#pragma unroll
    for (int off = 16; off >= 1; off >>= 1)
        m = fmaxf(m, __shfl_xor_sync(0xffffffffu, m, off));
    if (lane == 0) red[warp] = m;
    __syncthreads();
    m = red[0];
#pragma unroll
    for (int w = 1; w < 8; w++) m = fmaxf(m, red[w]);

    float e0 = (j0 + 0 <= i) ? expf(s0 - m) : 0.f;
    float e1 = (j0 + 1 <= i) ? expf(s1 - m) : 0.f;
    float e2 = (j0 + 2 <= i) ? expf(s2 - m) : 0.f;
    float e3 = (j0 + 3 <= i) ? expf(s3 - m) : 0.f;
    float lsum = e0 + e1 + e2 + e3;

    __syncthreads();
#pragma unroll
    for (int off = 16; off >= 1; off >>= 1)
        lsum += __shfl_xor_sync(0xffffffffu, lsum, off);
    if (lane == 0) red[warp] = lsum;
    __syncthreads();
    float tot = red[0];
#pragma unroll
    for (int w = 1; w < 8; w++) tot += red[w];
    const float inv = 1.f / tot;

    __half2 h0 = __floats2half2_rn(e0 * inv, e1 * inv);
    __half2 h1 = __floats2half2_rn(e2 * inv, e3 * inv);
    __half2 hp[2] = {h0, h1};
    *(uint2*)(prow + j0) = *(const uint2*)hp;
}

// ---- Stage 4: O = P V (fp32 out), causal K-limit ----
__global__ void __launch_bounds__(NTHREADS, 2) pv_kernel(float* __restrict__ out) {
    const int b = blockIdx.z;
    const int m0 = blockIdx.y * BM;
    const __half* P = g_P + (size_t)b * TT * TT;
    const __half* V = g_V + (size_t)b * TT * DD;
    float* O = out + (size_t)b * TT * DD;
    const int KT = (m0 + BM) / BK;   // only k <= m0+127 can be nonzero
    gemm_body<false, false, false, false>(P, V, nullptr, O, nullptr,
                                          m0, blockIdx.x * BN,
                                          KT, TT, DD, DD, 1.f);
}

extern "C" void kernel_launch(void* const* d_in, const int* in_sizes, int n_in,
                              void* d_out, int out_size) {
    const float* qe = (const float*)d_in[0];
    const float* ke = (const float*)d_in[1];
    const float* ve = (const float*)d_in[2];
    const float* Wq = (const float*)d_in[3];
    const float* bq = (const float*)d_in[4];
    const float* Wk = (const float*)d_in[5];
    const float* bk = (const float*)d_in[6];
    const float* Wv = (const float*)d_in[7];
    const float* bv = (const float*)d_in[8];
    float* out = (float*)d_out;

    cudaFuncSetAttribute(proj_kernel, cudaFuncAttributeMaxDynamicSharedMemorySize, SMEM_T);
    cudaFuncSetAttribute(qk_kernel,   cudaFuncAttributeMaxDynamicSharedMemorySize, SMEM_T);
    cudaFuncSetAttribute(pv_kernel,   cudaFuncAttributeMaxDynamicSharedMemorySize, SMEM_N);

    roundX_kernel<<<dim3(16777216 / 8 / 256, 3), 256>>>(qe, ke, ve);
    roundW_kernel<<<dim3(1048576 / 8 / 256, 3), 256>>>(Wq, Wk, Wv);
    proj_kernel<<<dim3(DD / BN, (BB * TT) / BM, 3), NTHREADS, SMEM_T>>>(bq, bk, bv);
    qk_kernel<<<dim3(TT / BN, TT / BM, BB), NTHREADS, SMEM_T>>>();
    softmax_kernel<<<dim3(BB * TT), 256>>>();
    pv_kernel<<<dim3(DD / BN, TT / BM, BB), NTHREADS, SMEM_N>>>(out);
}